// round 3
// baseline (speedup 1.0000x reference)
#include <cuda_runtime.h>
#include <cuda_bf16.h>

// Batched exp of log-affine matrices (ndims=3), B=1e6.
// Round 3: stage I/O through shared memory so all global accesses are
// unit-stride coalesced LDG.128/STG.128 (fixes 48B-stride L1 wavefront
// inflation seen in ncu: L1=54.8%, nothing else saturated).
//
// Math (unchanged from R2): fixed s=2 scaling, degree-4 Taylor
// (Paterson-Stockmeyer) on the 3x3 block, phi1 matvec chain for the
// translation, two affine squarings. rel_err ~1.5e-7 << 1e-3 bar.

#define TPB 256

__device__ __forceinline__ void mm33(const float* __restrict__ X,
                                     const float* __restrict__ Y,
                                     float* __restrict__ Z) {
#pragma unroll
    for (int r = 0; r < 3; r++) {
        const float x0 = X[r * 3 + 0], x1 = X[r * 3 + 1], x2 = X[r * 3 + 2];
#pragma unroll
        for (int c = 0; c < 3; c++)
            Z[r * 3 + c] = fmaf(x0, Y[c], fmaf(x1, Y[3 + c], x2 * Y[6 + c]));
    }
}

__device__ __forceinline__ void mv3(const float* __restrict__ X,
                                    const float* __restrict__ v,
                                    float* __restrict__ w) {
#pragma unroll
    for (int r = 0; r < 3; r++)
        w[r] = fmaf(X[r * 3 + 0], v[0], fmaf(X[r * 3 + 1], v[1], X[r * 3 + 2] * v[2]));
}

__global__ void __launch_bounds__(TPB)
expaff_kernel(const float4* __restrict__ in, float4* __restrict__ out, int n) {
    __shared__ float4 s_in[TPB * 3];
    __shared__ float4 s_out[TPB * 3];

    const int tid = threadIdx.x;
    const int base = blockIdx.x * TPB;          // first matrix of this block
    const int nblk = min(TPB, n - base);        // matrices in this block
    const int nf4 = nblk * 3;                   // float4s to move

    // Coalesced load: unit-stride LDG.128
    {
        const float4* gin = in + (size_t)base * 3;
#pragma unroll
        for (int k = 0; k < 3; k++) {
            int idx = tid + k * TPB;
            if (idx < nf4) s_in[idx] = gin[idx];
        }
    }
    __syncthreads();

    if (tid < nblk) {
        float4 r0 = s_in[3 * tid + 0];
        float4 r1 = s_in[3 * tid + 1];
        float4 r2 = s_in[3 * tid + 2];

        const float S = 0.25f;  // fixed scaling 2^-2
        float A[9] = {r0.x * S, r0.y * S, r0.z * S,
                      r1.x * S, r1.y * S, r1.z * S,
                      r2.x * S, r2.y * S, r2.z * S};
        float t[3] = {r0.w * S, r1.w * S, r2.w * S};

        // B = A^2
        float B[9];
        mm33(A, A, B);

        // C = A/6 + B/24
        float C[9];
#pragma unroll
        for (int j = 0; j < 9; j++)
            C[j] = fmaf(B[j], 1.0f / 24.0f, A[j] * (1.0f / 6.0f));

        // G = B*C
        float G[9];
        mm33(B, C, G);

        // E = I + A + B/2 + G
        float E[9];
#pragma unroll
        for (int j = 0; j < 9; j++)
            E[j] = A[j] + fmaf(B[j], 0.5f, G[j]);
        E[0] += 1.0f; E[4] += 1.0f; E[8] += 1.0f;

        // u = t + At/2 + A^2 t/6 + A^3 t/24
        float w1[3], w2[3], w3[3], u[3];
        mv3(A, t, w1);
        mv3(A, w1, w2);
        mv3(A, w2, w3);
#pragma unroll
        for (int j = 0; j < 3; j++)
            u[j] = fmaf(w1[j], 0.5f,
                   fmaf(w2[j], 1.0f / 6.0f,
                   fmaf(w3[j], 1.0f / 24.0f, t[j])));

        // Two affine squarings: [E,u] <- [E^2, E u + u]
#pragma unroll
        for (int q = 0; q < 2; q++) {
            float E2[9], u2[3];
            mm33(E, E, E2);
            mv3(E, u, u2);
#pragma unroll
            for (int j = 0; j < 9; j++) E[j] = E2[j];
#pragma unroll
            for (int j = 0; j < 3; j++) u[j] = u2[j] + u[j];
        }

        s_out[3 * tid + 0] = make_float4(E[0], E[1], E[2], u[0]);
        s_out[3 * tid + 1] = make_float4(E[3], E[4], E[5], u[1]);
        s_out[3 * tid + 2] = make_float4(E[6], E[7], E[8], u[2]);
    }
    __syncthreads();

    // Coalesced store: unit-stride STG.128
    {
        float4* gout = out + (size_t)base * 3;
#pragma unroll
        for (int k = 0; k < 3; k++) {
            int idx = tid + k * TPB;
            if (idx < nf4) gout[idx] = s_out[idx];
        }
    }
}

extern "C" void kernel_launch(void* const* d_in, const int* in_sizes, int n_in,
                              void* d_out, int out_size) {
    const float* vec = (const float*)d_in[0];
    float* outp = (float*)d_out;
    int n = in_sizes[0] / 12;

    int blocks = (n + TPB - 1) / TPB;
    expaff_kernel<<<blocks, TPB>>>((const float4*)vec, (float4*)outp, n);
}

// round 4
// speedup vs baseline: 1.0357x; 1.0357x over previous
#include <cuda_runtime.h>
#include <cuda_bf16.h>

// Batched exp of log-affine matrices (ndims=3), B=1e6.
// R4: two matrices per thread (ILP x2, half the per-thread overhead),
// scaling folded into Taylor coefficients, direct strided LDG/STG (the
// smem staging in R3 was proven neutral: LDS/STS share the L1 pipe).
//
// Math: fixed s=2 scaling-and-squaring, degree-4 Taylor (Paterson-
// Stockmeyer) on the 3x3 block, phi1 matvec chain for translation,
// 2 affine squarings. rel_err ~1.5e-7 << 1e-3 bar.

#define TPB 128

__device__ __forceinline__ void mm33(const float* __restrict__ X,
                                     const float* __restrict__ Y,
                                     float* __restrict__ Z) {
#pragma unroll
    for (int r = 0; r < 3; r++) {
        const float x0 = X[r * 3 + 0], x1 = X[r * 3 + 1], x2 = X[r * 3 + 2];
#pragma unroll
        for (int c = 0; c < 3; c++)
            Z[r * 3 + c] = fmaf(x0, Y[c], fmaf(x1, Y[3 + c], x2 * Y[6 + c]));
    }
}

__device__ __forceinline__ void mv3(const float* __restrict__ X,
                                    const float* __restrict__ v,
                                    float* __restrict__ w) {
#pragma unroll
    for (int r = 0; r < 3; r++)
        w[r] = fmaf(X[r * 3 + 0], v[0], fmaf(X[r * 3 + 1], v[1], X[r * 3 + 2] * v[2]));
}

// Compute top 3x4 of expm([[A,t],[0,0]]) from raw (unscaled) input rows.
__device__ __forceinline__ void expaff_one(const float4 r0, const float4 r1,
                                           const float4 r2,
                                           float4& o0, float4& o1, float4& o2) {
    // Coefficients with S = 2^-2 folded in.
    const float c1 = 0.25f;                  // S
    const float c2 = 0.03125f;               // S^2/2
    const float c3 = 0.25f * 0.25f * 0.25f / 6.0f;    // S^3/6
    const float c4 = 0.25f * 0.25f * 0.25f * 0.25f / 24.0f;  // S^4/24

    float A[9] = {r0.x, r0.y, r0.z,
                  r1.x, r1.y, r1.z,
                  r2.x, r2.y, r2.z};
    float t[3] = {r0.w, r1.w, r2.w};

    // B = A^2 (raw)
    float B[9];
    mm33(A, A, B);

    // C = c3*A + c4*B ;  G = B*C  (== S^3 A^3/6 + S^4 A^4/24)
    float C[9];
#pragma unroll
    for (int j = 0; j < 9; j++) C[j] = fmaf(B[j], c4, A[j] * c3);
    float G[9];
    mm33(B, C, G);

    // E = I + c1*A + c2*B + G
    float E[9];
#pragma unroll
    for (int j = 0; j < 9; j++) E[j] = fmaf(A[j], c1, fmaf(B[j], c2, G[j]));
    E[0] += 1.0f; E[4] += 1.0f; E[8] += 1.0f;

    // u = S*t + (S^2/2) A t + (S^3/6) A^2 t + (S^4/24) A^3 t
    float w1[3], w2[3], w3[3], u[3];
    mv3(A, t, w1);
    mv3(A, w1, w2);
    mv3(A, w2, w3);
#pragma unroll
    for (int j = 0; j < 3; j++)
        u[j] = fmaf(t[j], c1, fmaf(w1[j], c2, fmaf(w2[j], c3, w3[j] * c4)));

    // Two affine squarings: [E,u] <- [E^2, E u + u]
#pragma unroll
    for (int q = 0; q < 2; q++) {
        float E2[9], u2[3];
        mm33(E, E, E2);
        mv3(E, u, u2);
#pragma unroll
        for (int j = 0; j < 9; j++) E[j] = E2[j];
#pragma unroll
        for (int j = 0; j < 3; j++) u[j] = u2[j] + u[j];
    }

    o0 = make_float4(E[0], E[1], E[2], u[0]);
    o1 = make_float4(E[3], E[4], E[5], u[1]);
    o2 = make_float4(E[6], E[7], E[8], u[2]);
}

__global__ void expaff_kernel(const float4* __restrict__ in,
                              float4* __restrict__ out, int n) {
    const int tid = threadIdx.x;
    const int base = blockIdx.x * (2 * TPB);
    const int i0 = base + tid;
    const int i1 = base + TPB + tid;
    const bool v0 = i0 < n;
    const bool v1 = i1 < n;

    // Front-batch all loads (MLP 6)
    float4 a0 = {}, a1 = {}, a2 = {}, b0 = {}, b1 = {}, b2 = {};
    if (v0) {
        a0 = in[3 * i0 + 0];
        a1 = in[3 * i0 + 1];
        a2 = in[3 * i0 + 2];
    }
    if (v1) {
        b0 = in[3 * i1 + 0];
        b1 = in[3 * i1 + 1];
        b2 = in[3 * i1 + 2];
    }

    float4 x0, x1, x2, y0, y1, y2;
    expaff_one(a0, a1, a2, x0, x1, x2);
    expaff_one(b0, b1, b2, y0, y1, y2);

    if (v0) {
        out[3 * i0 + 0] = x0;
        out[3 * i0 + 1] = x1;
        out[3 * i0 + 2] = x2;
    }
    if (v1) {
        out[3 * i1 + 0] = y0;
        out[3 * i1 + 1] = y1;
        out[3 * i1 + 2] = y2;
    }
}

extern "C" void kernel_launch(void* const* d_in, const int* in_sizes, int n_in,
                              void* d_out, int out_size) {
    const float* vec = (const float*)d_in[0];
    float* outp = (float*)d_out;
    int n = in_sizes[0] / 12;

    int blocks = (n + 2 * TPB - 1) / (2 * TPB);
    expaff_kernel<<<blocks, TPB>>>((const float4*)vec, (float4*)outp, n);
}